// round 3
// baseline (speedup 1.0000x reference)
#include <cuda_runtime.h>
#include <math.h>
#include <float.h>

#define NNODES 50000
#define D 128
#define S 25
#define BLK_M 64
#define KB 32
#define NPART 512

// ---------------- scratch (device globals; no allocation) ----------------
__device__ float g_h[NNODES * D];     // relu(linear) table for maxpool (layer1 & layer2)
__device__ float g_agg[NNODES * D];   // max-pooled aggregation
__device__ float g_x[NNODES * D];     // fc1 output (pre-BN)
__device__ float g_xn[NNODES * D];    // post BN + L2-normalize
__device__ float g_part[NPART * 2 * D];
__device__ float g_scale[D];
__device__ float g_shift[D];

// ---------------- GEMM: C[M,128] = act( [A1|A2][M,KTOT] @ W[KTOT,128] + b ) ----
// Block: 64 rows x 128 cols, 256 threads, thread tile 8 rows x 4 cols.
// K staged in 32-deep chunks. A2 supplies K rows [128,256) for concat GEMMs.
template <int KTOT, bool RELU>
__global__ __launch_bounds__(256) void gemm_kernel(
    const float* __restrict__ A1, const float* __restrict__ A2,
    const float* __restrict__ W, const float* __restrict__ bias,
    float* __restrict__ C, int M)
{
    __shared__ float Ws[KB][D];            // 16 KB
    __shared__ float As[KB][BLK_M + 1];    // 8.1 KB (padded: conflict-free stores)

    const int t  = threadIdx.x;
    const int tx = t & 31;       // 32 col-groups
    const int ty = t >> 5;       // 8 row-groups
    const int c0 = tx * 4;
    const int r0 = ty * 8;
    const int m0 = blockIdx.x * BLK_M;

    float acc[8][4];
#pragma unroll
    for (int i = 0; i < 8; i++) {
        acc[i][0] = 0.f; acc[i][1] = 0.f; acc[i][2] = 0.f; acc[i][3] = 0.f;
    }

    for (int kc = 0; kc < KTOT; kc += KB) {
        const float* __restrict__ A = (KTOT == 256 && kc >= 128) ? A2 : A1;
        const int kl = kc & (D - 1);

        // A tile: rows m0..m0+63, cols kl..kl+31 (coalesced loads, padded stores)
#pragma unroll
        for (int rr = 0; rr < BLK_M; rr += 8) {
            int row = rr + ty;
            int gr  = m0 + row;
            As[tx][row] = (gr < M) ? A[(long)gr * D + kl + tx] : 0.f;
        }
        // W chunk: rows kc..kc+31 of W[*,128]
#pragma unroll
        for (int i = 0; i < (KB * D) / 256; i++) {
            int idx = i * 256 + t;
            int kk  = idx >> 7;
            int cc  = idx & (D - 1);
            Ws[kk][cc] = W[(long)(kc + kk) * D + cc];
        }
        __syncthreads();

#pragma unroll
        for (int kk = 0; kk < KB; kk++) {
            float4 w = *(const float4*)&Ws[kk][c0];
#pragma unroll
            for (int i = 0; i < 8; i++) {
                float a = As[kk][r0 + i];
                acc[i][0] = fmaf(a, w.x, acc[i][0]);
                acc[i][1] = fmaf(a, w.y, acc[i][1]);
                acc[i][2] = fmaf(a, w.z, acc[i][2]);
                acc[i][3] = fmaf(a, w.w, acc[i][3]);
            }
        }
        __syncthreads();
    }

    float4 bv = *(const float4*)&bias[c0];
#pragma unroll
    for (int i = 0; i < 8; i++) {
        int gr = m0 + r0 + i;
        if (gr < M) {
            float4 o;
            o.x = acc[i][0] + bv.x;
            o.y = acc[i][1] + bv.y;
            o.z = acc[i][2] + bv.z;
            o.w = acc[i][3] + bv.w;
            if (RELU) {
                o.x = fmaxf(o.x, 0.f); o.y = fmaxf(o.y, 0.f);
                o.z = fmaxf(o.z, 0.f); o.w = fmaxf(o.w, 0.f);
            }
            *(float4*)&C[(long)gr * D + c0] = o;
        }
    }
}

// ---------------- max-pool over S sampled neighbors (warp per node) -----------
__global__ void maxpool_kernel(const float* __restrict__ H,
                               const int* __restrict__ idx,
                               float* __restrict__ out)
{
    int w = (blockIdx.x * blockDim.x + threadIdx.x) >> 5;
    if (w >= NNODES) return;
    int lane = threadIdx.x & 31;
    const int* ip = idx + (long)w * S;
    float4 m = make_float4(-FLT_MAX, -FLT_MAX, -FLT_MAX, -FLT_MAX);
#pragma unroll 5
    for (int s = 0; s < S; s++) {
        int r = __ldg(&ip[s]);
        float4 v = *(const float4*)&H[(long)r * D + lane * 4];
        m.x = fmaxf(m.x, v.x); m.y = fmaxf(m.y, v.y);
        m.z = fmaxf(m.z, v.z); m.w = fmaxf(m.w, v.w);
    }
    *(float4*)&out[(long)w * D + lane * 4] = m;
}

// ---------------- BN stats: deterministic two-stage column reduction ----------
__global__ void stats_partial_kernel()
{
    int c = threadIdx.x;  // 128 threads, one column each
    float s = 0.f, s2 = 0.f;
    for (int r = blockIdx.x; r < NNODES; r += NPART) {
        float v = g_x[(long)r * D + c];
        s  += v;
        s2 += v * v;
    }
    g_part[blockIdx.x * (2 * D) + c]     = s;
    g_part[blockIdx.x * (2 * D) + D + c] = s2;
}

__global__ void stats_final_kernel(const float* __restrict__ gamma,
                                   const float* __restrict__ beta)
{
    int c = threadIdx.x;  // 128
    float s = 0.f, s2 = 0.f;
    for (int b = 0; b < NPART; b++) {
        s  += g_part[b * (2 * D) + c];
        s2 += g_part[b * (2 * D) + D + c];
    }
    float invn = 1.f / (float)NNODES;
    float mean = s * invn;
    float var  = s2 * invn - mean * mean;
    float sc   = gamma[c] * rsqrtf(var + 1e-5f);
    g_scale[c] = sc;
    g_shift[c] = fmaf(-mean, sc, beta[c]);
}

// ---------------- BN apply + L2 row-normalize (warp per row) ------------------
__global__ void bn_norm_kernel(const float* __restrict__ X,
                               float* __restrict__ out)
{
    int w = (blockIdx.x * blockDim.x + threadIdx.x) >> 5;
    if (w >= NNODES) return;
    int lane = threadIdx.x & 31;
    int c = lane * 4;
    float4 v  = *(const float4*)&X[(long)w * D + c];
    float4 sc = *(const float4*)&g_scale[c];
    float4 sh = *(const float4*)&g_shift[c];
    v.x = fmaf(v.x, sc.x, sh.x);
    v.y = fmaf(v.y, sc.y, sh.y);
    v.z = fmaf(v.z, sc.z, sh.z);
    v.w = fmaf(v.w, sc.w, sh.w);
    float ss = v.x * v.x + v.y * v.y + v.z * v.z + v.w * v.w;
#pragma unroll
    for (int o = 16; o > 0; o >>= 1) ss += __shfl_xor_sync(0xffffffffu, ss, o);
    float inv = 1.f / (sqrtf(ss) + 1e-6f);
    v.x *= inv; v.y *= inv; v.z *= inv; v.w *= inv;
    *(float4*)&out[(long)w * D + c] = v;
}

// ---------------- launch ------------------------------------------------------
extern "C" void kernel_launch(void* const* d_in, const int* in_sizes, int n_in,
                              void* d_out, int out_size)
{
    const float* features = (const float*)d_in[0];
    const int*   idx1     = (const int*)d_in[1];
    const int*   idx2     = (const int*)d_in[2];
    const float* agg1_W   = (const float*)d_in[3];
    const float* agg1_b   = (const float*)d_in[4];
    const float* fc1_W    = (const float*)d_in[5];
    const float* fc1_b    = (const float*)d_in[6];
    const float* agg2_W   = (const float*)d_in[7];
    const float* agg2_b   = (const float*)d_in[8];
    const float* fc2_W    = (const float*)d_in[9];
    const float* fc2_b    = (const float*)d_in[10];
    const float* gamma    = (const float*)d_in[11];
    const float* beta     = (const float*)d_in[12];
    float* out = (float*)d_out;

    float *ph, *pagg, *px, *pxn;
    cudaGetSymbolAddress((void**)&ph,   g_h);
    cudaGetSymbolAddress((void**)&pagg, g_agg);
    cudaGetSymbolAddress((void**)&px,   g_x);
    cudaGetSymbolAddress((void**)&pxn,  g_xn);

    const int gemm_grid = (NNODES + BLK_M - 1) / BLK_M;                 // 782
    const int warp_grid = (NNODES * 32 + 255) / 256;                    // 6250

    // ---- layer 1 ----
    gemm_kernel<128, true><<<gemm_grid, 256>>>(features, nullptr, agg1_W, agg1_b, ph, NNODES);
    maxpool_kernel<<<warp_grid, 256>>>(ph, idx1, pagg);
    gemm_kernel<256, true><<<gemm_grid, 256>>>(features, pagg, fc1_W, fc1_b, px, NNODES);
    stats_partial_kernel<<<NPART, D>>>();
    stats_final_kernel<<<1, D>>>(gamma, beta);
    bn_norm_kernel<<<warp_grid, 256>>>(px, pxn);
    // ---- layer 2 ----
    gemm_kernel<128, true><<<gemm_grid, 256>>>(pxn, nullptr, agg2_W, agg2_b, ph, NNODES);
    maxpool_kernel<<<warp_grid, 256>>>(ph, idx2, pagg);
    gemm_kernel<256, false><<<gemm_grid, 256>>>(pxn, pagg, fc2_W, fc2_b, out, NNODES);
}

// round 14
// speedup vs baseline: 1.3767x; 1.3767x over previous
#include <cuda_runtime.h>
#include <cuda_bf16.h>
#include <stdint.h>
#include <math.h>
#include <float.h>

#define NNODES 50000
#define D 128
#define S 25
#define NPART 512

#define ROWP 136                    // padded row length in bf16 elems (128 + 8)
#define PS   (128 * ROWP)           // plane size in shorts = 17408

// -------------------- scratch (device globals; no allocation) ----------------
__device__ float g_h[NNODES * D];
__device__ float g_agg[NNODES * D];
__device__ float g_x[NNODES * D];
__device__ float g_xn[NNODES * D];
__device__ float g_part[NPART * 2 * D];
__device__ float g_scale[D];
__device__ float g_shift[D];
// 6 weight K-chunks (agg1, fc1a, fc1b, agg2, fc2a, fc2b) x {hi,lo} planes,
// each plane [n][k] padded to ROWP
__device__ __align__(16) unsigned short g_wfmt[6 * 2 * PS];

__device__ __forceinline__ unsigned short bf16_hi(float x) {
    return __bfloat16_as_ushort(__float2bfloat16(x));
}
__device__ __forceinline__ float bf16_val(unsigned short u) {
    return __bfloat162float(__ushort_as_bfloat16(u));
}

// -------------------- weight pre-format (once per launch) --------------------
// Plane layout: Bs[n][k] = W[kc+k][n], rows padded to ROWP shorts.
__global__ void prep_weights(const float* __restrict__ agg1W, const float* __restrict__ fc1W,
                             const float* __restrict__ agg2W, const float* __restrict__ fc2W)
{
    int b = blockIdx.x;
    const float* W; int kc;
    switch (b) {
        case 0: W = agg1W; kc = 0;   break;
        case 1: W = fc1W;  kc = 0;   break;
        case 2: W = fc1W;  kc = 128; break;
        case 3: W = agg2W; kc = 0;   break;
        case 4: W = fc2W;  kc = 0;   break;
        default: W = fc2W; kc = 128; break;
    }
    unsigned short* hi = g_wfmt + (b * 2 + 0) * PS;
    unsigned short* lo = g_wfmt + (b * 2 + 1) * PS;
    int t = threadIdx.x;
    int n  = t & 127;
    int k0 = (t >> 7) * 64;
    for (int k = 0; k < 64; k++) {
        float x = W[(long)(kc + k0 + k) * 128 + n];
        unsigned short h = bf16_hi(x);
        unsigned short l = bf16_hi(x - bf16_val(h));
        hi[n * ROWP + k0 + k] = h;
        lo[n * ROWP + k0 + k] = l;
    }
}

// -------------------- HMMA (mma.sync) helpers --------------------------------
__device__ __forceinline__ void mma16816(float* c,
                                         uint32_t a0, uint32_t a1, uint32_t a2, uint32_t a3,
                                         uint32_t b0, uint32_t b1)
{
    asm volatile(
        "mma.sync.aligned.m16n8k16.row.col.f32.bf16.bf16.f32 "
        "{%0,%1,%2,%3}, {%4,%5,%6,%7}, {%8,%9}, {%0,%1,%2,%3};"
        : "+f"(c[0]), "+f"(c[1]), "+f"(c[2]), "+f"(c[3])
        : "r"(a0), "r"(a1), "r"(a2), "r"(a3), "r"(b0), "r"(b1));
}

// -------------------- HMMA GEMM ----------------------------------------------
// C[M,128] = act( [A1|A2][M,KTOT] @ W[KTOT,128] + b ), KTOT in {128,256}
// 3-term bf16 split: AhiBhi + AhiBlo + AloBhi (fp32 accum).
#define SMEM_TOTAL (4 * PS * 2)     // 4 planes of 34816 B = 139264 B

template <int KTOT, bool RELU>
__global__ __launch_bounds__(256) void hmma_gemm(
    const float* __restrict__ A1, const float* __restrict__ A2,
    const unsigned short* __restrict__ wf0,   // [hi PS][lo PS] chunk0
    const unsigned short* __restrict__ wf1,   // chunk1 (or null)
    const float* __restrict__ bias, float* __restrict__ C, int M)
{
    extern __shared__ __align__(16) unsigned short sm[];
    unsigned short* Ahi = sm;
    unsigned short* Alo = sm + PS;
    unsigned short* Bhi = sm + 2 * PS;
    unsigned short* Blo = sm + 3 * PS;

    const int t    = threadIdx.x;
    const int w    = t >> 5;
    const int lane = t & 31;
    const int g    = lane >> 2;        // group id (0..7)
    const int tq   = lane & 3;         // thread-in-group
    const int r0   = (w & 3) * 32;     // warp M offset within tile
    const int n0   = (w >> 2) * 64;    // warp N offset
    const int m0   = blockIdx.x * 128;

    float acc[2][8][4];
#pragma unroll
    for (int ma = 0; ma < 2; ma++)
#pragma unroll
        for (int na = 0; na < 8; na++)
#pragma unroll
            for (int q = 0; q < 4; q++) acc[ma][na][q] = 0.f;

    const int NCHUNK = KTOT / 128;
    for (int ch = 0; ch < NCHUNK; ch++) {
        const float* Asrc = (ch == 0) ? A1 : A2;
        const unsigned short* wf = (ch == 0) ? wf0 : wf1;

        // ---- fill A planes: 4096 float4 reads, hi/lo split, padded stores ----
#pragma unroll
        for (int i = 0; i < 16; i++) {
            int idx4 = i * 256 + t;
            int row = idx4 >> 5;
            int c4  = (idx4 & 31) << 2;
            float4 v = make_float4(0.f, 0.f, 0.f, 0.f);
            if (m0 + row < M) v = *(const float4*)&Asrc[(long)(m0 + row) * 128 + c4];
            unsigned short h0 = bf16_hi(v.x), h1 = bf16_hi(v.y), h2 = bf16_hi(v.z), h3 = bf16_hi(v.w);
            unsigned short l0 = bf16_hi(v.x - bf16_val(h0));
            unsigned short l1 = bf16_hi(v.y - bf16_val(h1));
            unsigned short l2 = bf16_hi(v.z - bf16_val(h2));
            unsigned short l3 = bf16_hi(v.w - bf16_val(h3));
            int o = row * ROWP + c4;   // multiple of 4 shorts -> 8B aligned
            *(uint2*)&Ahi[o] = make_uint2((uint32_t)h0 | ((uint32_t)h1 << 16),
                                          (uint32_t)h2 | ((uint32_t)h3 << 16));
            *(uint2*)&Alo[o] = make_uint2((uint32_t)l0 | ((uint32_t)l1 << 16),
                                          (uint32_t)l2 | ((uint32_t)l3 << 16));
        }
        // ---- copy pre-formatted B planes (PS shorts = 2176 uint4 each) ----
        {
            const uint4* shi = (const uint4*)wf;
            const uint4* slo = (const uint4*)(wf + PS);
            uint4* dhi = (uint4*)Bhi;
            uint4* dlo = (uint4*)Blo;
#pragma unroll
            for (int i = 0; i < 8; i++) {
                dhi[i * 256 + t] = shi[i * 256 + t];
                dlo[i * 256 + t] = slo[i * 256 + t];
            }
            if (t < 128) {
                dhi[2048 + t] = shi[2048 + t];
                dlo[2048 + t] = slo[2048 + t];
            }
        }
        __syncthreads();

        // ---- 3 split terms x 8 k-steps of 16 ----
        for (int p = 0; p < 3; p++) {
            const unsigned short* pA = (p == 2) ? Alo : Ahi;
            const unsigned short* pB = (p == 1) ? Blo : Bhi;
#pragma unroll
            for (int k0 = 0; k0 < 128; k0 += 16) {
                const int ca = k0 + 2 * tq;
                uint32_t b0[8], b1[8];
#pragma unroll
                for (int na = 0; na < 8; na++) {
                    const unsigned short* bp = &pB[(n0 + na * 8 + g) * ROWP + ca];
                    b0[na] = *(const uint32_t*)bp;
                    b1[na] = *(const uint32_t*)(bp + 8);
                }
#pragma unroll
                for (int ma = 0; ma < 2; ma++) {
                    const unsigned short* ap = &pA[(r0 + ma * 16 + g) * ROWP + ca];
                    uint32_t a0 = *(const uint32_t*)ap;
                    uint32_t a1 = *(const uint32_t*)(ap + 8 * ROWP);
                    uint32_t a2 = *(const uint32_t*)(ap + 8);
                    uint32_t a3 = *(const uint32_t*)(ap + 8 * ROWP + 8);
#pragma unroll
                    for (int na = 0; na < 8; na++)
                        mma16816(acc[ma][na], a0, a1, a2, a3, b0[na], b1[na]);
                }
            }
        }
        __syncthreads();
    }

    // ---- epilogue: bias + act, direct float2 stores ----
#pragma unroll
    for (int ma = 0; ma < 2; ma++) {
#pragma unroll
        for (int na = 0; na < 8; na++) {
            int row = m0 + r0 + ma * 16 + g;
            int col = n0 + na * 8 + 2 * tq;
            float bx = __ldg(&bias[col]);
            float by = __ldg(&bias[col + 1]);
            if (row < M) {
                float x = acc[ma][na][0] + bx;
                float y = acc[ma][na][1] + by;
                if (RELU) { x = fmaxf(x, 0.f); y = fmaxf(y, 0.f); }
                *(float2*)&C[(long)row * 128 + col] = make_float2(x, y);
            }
            if (row + 8 < M) {
                float x = acc[ma][na][2] + bx;
                float y = acc[ma][na][3] + by;
                if (RELU) { x = fmaxf(x, 0.f); y = fmaxf(y, 0.f); }
                *(float2*)&C[(long)(row + 8) * 128 + col] = make_float2(x, y);
            }
        }
    }
}

// -------------------- max-pool over S neighbors (warp per node) --------------
__global__ void maxpool_kernel(const float* __restrict__ H,
                               const int* __restrict__ idx,
                               float* __restrict__ out)
{
    int w = (blockIdx.x * blockDim.x + threadIdx.x) >> 5;
    if (w >= NNODES) return;
    int lane = threadIdx.x & 31;
    const int* ip = idx + (long)w * S;
    float4 m = make_float4(-FLT_MAX, -FLT_MAX, -FLT_MAX, -FLT_MAX);
#pragma unroll 5
    for (int s = 0; s < S; s++) {
        int r = __ldg(&ip[s]);
        float4 v = *(const float4*)&H[(long)r * D + lane * 4];
        m.x = fmaxf(m.x, v.x); m.y = fmaxf(m.y, v.y);
        m.z = fmaxf(m.z, v.z); m.w = fmaxf(m.w, v.w);
    }
    *(float4*)&out[(long)w * D + lane * 4] = m;
}

// -------------------- BN stats (deterministic two-stage) ---------------------
__global__ void stats_partial_kernel()
{
    int c = threadIdx.x;
    float s = 0.f, s2 = 0.f;
    for (int r = blockIdx.x; r < NNODES; r += NPART) {
        float v = g_x[(long)r * D + c];
        s += v;
        s2 += v * v;
    }
    g_part[blockIdx.x * (2 * D) + c] = s;
    g_part[blockIdx.x * (2 * D) + D + c] = s2;
}

__global__ void stats_final_kernel(const float* __restrict__ gamma,
                                   const float* __restrict__ beta)
{
    int c = threadIdx.x;
    float s = 0.f, s2 = 0.f;
    for (int b = 0; b < NPART; b++) {
        s += g_part[b * (2 * D) + c];
        s2 += g_part[b * (2 * D) + D + c];
    }
    float invn = 1.f / (float)NNODES;
    float mean = s * invn;
    float var = s2 * invn - mean * mean;
    float sc = gamma[c] * rsqrtf(var + 1e-5f);
    g_scale[c] = sc;
    g_shift[c] = fmaf(-mean, sc, beta[c]);
}

// -------------------- BN apply + L2 row-normalize ----------------------------
__global__ void bn_norm_kernel(const float* __restrict__ X,
                               float* __restrict__ out)
{
    int w = (blockIdx.x * blockDim.x + threadIdx.x) >> 5;
    if (w >= NNODES) return;
    int lane = threadIdx.x & 31;
    int c = lane * 4;
    float4 v = *(const float4*)&X[(long)w * D + c];
    float4 sc = *(const float4*)&g_scale[c];
    float4 sh = *(const float4*)&g_shift[c];
    v.x = fmaf(v.x, sc.x, sh.x);
    v.y = fmaf(v.y, sc.y, sh.y);
    v.z = fmaf(v.z, sc.z, sh.z);
    v.w = fmaf(v.w, sc.w, sh.w);
    float ss = v.x * v.x + v.y * v.y + v.z * v.z + v.w * v.w;
#pragma unroll
    for (int o = 16; o > 0; o >>= 1) ss += __shfl_xor_sync(0xffffffffu, ss, o);
    float inv = 1.f / (sqrtf(ss) + 1e-6f);
    v.x *= inv; v.y *= inv; v.z *= inv; v.w *= inv;
    *(float4*)&out[(long)w * D + c] = v;
}

// -------------------- launch -------------------------------------------------
extern "C" void kernel_launch(void* const* d_in, const int* in_sizes, int n_in,
                              void* d_out, int out_size)
{
    const float* features = (const float*)d_in[0];
    const int*   idx1     = (const int*)d_in[1];
    const int*   idx2     = (const int*)d_in[2];
    const float* agg1_W   = (const float*)d_in[3];
    const float* agg1_b   = (const float*)d_in[4];
    const float* fc1_W    = (const float*)d_in[5];
    const float* fc1_b    = (const float*)d_in[6];
    const float* agg2_W   = (const float*)d_in[7];
    const float* agg2_b   = (const float*)d_in[8];
    const float* fc2_W    = (const float*)d_in[9];
    const float* fc2_b    = (const float*)d_in[10];
    const float* gamma    = (const float*)d_in[11];
    const float* beta     = (const float*)d_in[12];
    float* out = (float*)d_out;

    float *ph, *pagg, *px, *pxn;
    unsigned short* pwf;
    cudaGetSymbolAddress((void**)&ph, g_h);
    cudaGetSymbolAddress((void**)&pagg, g_agg);
    cudaGetSymbolAddress((void**)&px, g_x);
    cudaGetSymbolAddress((void**)&pxn, g_xn);
    cudaGetSymbolAddress((void**)&pwf, g_wfmt);

    cudaFuncSetAttribute(hmma_gemm<128, true>,  cudaFuncAttributeMaxDynamicSharedMemorySize, SMEM_TOTAL);
    cudaFuncSetAttribute(hmma_gemm<256, true>,  cudaFuncAttributeMaxDynamicSharedMemorySize, SMEM_TOTAL);
    cudaFuncSetAttribute(hmma_gemm<256, false>, cudaFuncAttributeMaxDynamicSharedMemorySize, SMEM_TOTAL);

    const unsigned short* wf_agg1 = pwf + 0 * (2 * PS);
    const unsigned short* wf_fc1a = pwf + 1 * (2 * PS);
    const unsigned short* wf_fc1b = pwf + 2 * (2 * PS);
    const unsigned short* wf_agg2 = pwf + 3 * (2 * PS);
    const unsigned short* wf_fc2a = pwf + 4 * (2 * PS);
    const unsigned short* wf_fc2b = pwf + 5 * (2 * PS);

    const int gemm_grid = (NNODES + 127) / 128;          // 391
    const int warp_grid = (NNODES * 32 + 255) / 256;     // 6250

    prep_weights<<<6, 256>>>(agg1_W, fc1_W, agg2_W, fc2_W);

    // ---- layer 1 ----
    hmma_gemm<128, true><<<gemm_grid, 256, SMEM_TOTAL>>>(features, nullptr, wf_agg1, nullptr, agg1_b, ph, NNODES);
    maxpool_kernel<<<warp_grid, 256>>>(ph, idx1, pagg);
    hmma_gemm<256, true><<<gemm_grid, 256, SMEM_TOTAL>>>(features, pagg, wf_fc1a, wf_fc1b, fc1_b, px, NNODES);
    stats_partial_kernel<<<NPART, D>>>();
    stats_final_kernel<<<1, D>>>(gamma, beta);
    bn_norm_kernel<<<warp_grid, 256>>>(px, pxn);
    // ---- layer 2 ----
    hmma_gemm<128, true><<<gemm_grid, 256, SMEM_TOTAL>>>(pxn, nullptr, wf_agg2, nullptr, agg2_b, ph, NNODES);
    maxpool_kernel<<<warp_grid, 256>>>(ph, idx2, pagg);
    hmma_gemm<256, false><<<gemm_grid, 256, SMEM_TOTAL>>>(pxn, pagg, wf_fc2a, wf_fc2b, fc2_b, out, NNODES);
}

// round 15
// speedup vs baseline: 1.4203x; 1.0317x over previous
#include <cuda_runtime.h>
#include <cuda_bf16.h>
#include <stdint.h>
#include <math.h>
#include <float.h>

#define NNODES 50000
#define D 128
#define S 25
#define NPART 512

#define ROWP 136                    // padded row length in bf16 elems (128 + 8)
#define PS   (128 * ROWP)           // B plane size in shorts = 17408
#define BLKM 64
#define APS  (BLKM * ROWP)          // A plane size in shorts = 8704

// -------------------- scratch (device globals; no allocation) ----------------
__device__ float g_h[NNODES * D];
__device__ float g_agg[NNODES * D];
__device__ float g_x[NNODES * D];
__device__ float g_xn[NNODES * D];
__device__ float g_part[NPART * 2 * D];
__device__ float g_scale[D];
__device__ float g_shift[D];
// 6 weight K-chunks (agg1, fc1a, fc1b, agg2, fc2a, fc2b) x {hi,lo} planes
__device__ __align__(16) unsigned short g_wfmt[6 * 2 * PS];

__device__ __forceinline__ unsigned short bf16_hi(float x) {
    return __bfloat16_as_ushort(__float2bfloat16(x));
}
__device__ __forceinline__ float bf16_val(unsigned short u) {
    return __bfloat162float(__ushort_as_bfloat16(u));
}

// -------------------- weight pre-format (once per launch) --------------------
// Plane layout: Bs[n][k] = W[kc+k][n], rows padded to ROWP shorts.
__global__ void prep_weights(const float* __restrict__ agg1W, const float* __restrict__ fc1W,
                             const float* __restrict__ agg2W, const float* __restrict__ fc2W)
{
    int b = blockIdx.x;
    const float* W; int kc;
    switch (b) {
        case 0: W = agg1W; kc = 0;   break;
        case 1: W = fc1W;  kc = 0;   break;
        case 2: W = fc1W;  kc = 128; break;
        case 3: W = agg2W; kc = 0;   break;
        case 4: W = fc2W;  kc = 0;   break;
        default: W = fc2W; kc = 128; break;
    }
    unsigned short* hi = g_wfmt + (b * 2 + 0) * PS;
    unsigned short* lo = g_wfmt + (b * 2 + 1) * PS;
    int t = threadIdx.x;
    int n  = t & 127;
    int k0 = (t >> 7) * 64;
    for (int k = 0; k < 64; k++) {
        float x = W[(long)(kc + k0 + k) * 128 + n];
        unsigned short h = bf16_hi(x);
        unsigned short l = bf16_hi(x - bf16_val(h));
        hi[n * ROWP + k0 + k] = h;
        lo[n * ROWP + k0 + k] = l;
    }
}

// -------------------- HMMA (mma.sync) helpers --------------------------------
__device__ __forceinline__ void mma16816(float* c,
                                         uint32_t a0, uint32_t a1, uint32_t a2, uint32_t a3,
                                         uint32_t b0, uint32_t b1)
{
    asm volatile(
        "mma.sync.aligned.m16n8k16.row.col.f32.bf16.bf16.f32 "
        "{%0,%1,%2,%3}, {%4,%5,%6,%7}, {%8,%9}, {%0,%1,%2,%3};"
        : "+f"(c[0]), "+f"(c[1]), "+f"(c[2]), "+f"(c[3])
        : "r"(a0), "r"(a1), "r"(a2), "r"(a3), "r"(b0), "r"(b1));
}

// -------------------- HMMA GEMM ----------------------------------------------
// C[M,128] = act( [A1|A2][M,KTOT] @ W[KTOT,128] + b ), KTOT in {128,256}
// 3-term bf16 split: AhiBhi + AhiBlo + AloBhi (fp32 accum).
// CTA tile: 64 rows x 128 cols; 8 warps = 2(M) x 4(N); warp tile 32x32.
#define SMEM_TOTAL ((2 * APS + 2 * PS) * 2)   // 104448 B -> 2 CTAs/SM

template <int KTOT, bool RELU>
__global__ __launch_bounds__(256) void hmma_gemm(
    const float* __restrict__ A1, const float* __restrict__ A2,
    const unsigned short* __restrict__ wf0,   // [hi PS][lo PS] chunk0
    const unsigned short* __restrict__ wf1,   // chunk1 (or null)
    const float* __restrict__ bias, float* __restrict__ C, int M)
{
    extern __shared__ __align__(16) unsigned short sm[];
    unsigned short* Ahi = sm;
    unsigned short* Alo = sm + APS;
    unsigned short* Bhi = sm + 2 * APS;
    unsigned short* Blo = sm + 2 * APS + PS;

    const int t    = threadIdx.x;
    const int w    = t >> 5;
    const int lane = t & 31;
    const int g    = lane >> 2;        // group id (0..7)
    const int tq   = lane & 3;         // thread-in-group
    const int r0   = (w & 1) * 32;     // warp M offset within tile
    const int n0   = (w >> 1) * 32;    // warp N offset
    const int m0   = blockIdx.x * BLKM;

    float acc[2][4][4];
#pragma unroll
    for (int ma = 0; ma < 2; ma++)
#pragma unroll
        for (int na = 0; na < 4; na++)
#pragma unroll
            for (int q = 0; q < 4; q++) acc[ma][na][q] = 0.f;

    const int NCHUNK = KTOT / 128;
    for (int ch = 0; ch < NCHUNK; ch++) {
        const float* Asrc = (ch == 0) ? A1 : A2;
        const unsigned short* wf = (ch == 0) ? wf0 : wf1;

        // ---- fill A planes: 2048 float4 reads, hi/lo split, padded stores ----
#pragma unroll
        for (int i = 0; i < 8; i++) {
            int idx4 = i * 256 + t;
            int row = idx4 >> 5;
            int c4  = (idx4 & 31) << 2;
            float4 v = make_float4(0.f, 0.f, 0.f, 0.f);
            if (m0 + row < M) v = *(const float4*)&Asrc[(long)(m0 + row) * 128 + c4];
            unsigned short h0 = bf16_hi(v.x), h1 = bf16_hi(v.y), h2 = bf16_hi(v.z), h3 = bf16_hi(v.w);
            unsigned short l0 = bf16_hi(v.x - bf16_val(h0));
            unsigned short l1 = bf16_hi(v.y - bf16_val(h1));
            unsigned short l2 = bf16_hi(v.z - bf16_val(h2));
            unsigned short l3 = bf16_hi(v.w - bf16_val(h3));
            int o = row * ROWP + c4;   // multiple of 4 shorts -> 8B aligned
            *(uint2*)&Ahi[o] = make_uint2((uint32_t)h0 | ((uint32_t)h1 << 16),
                                          (uint32_t)h2 | ((uint32_t)h3 << 16));
            *(uint2*)&Alo[o] = make_uint2((uint32_t)l0 | ((uint32_t)l1 << 16),
                                          (uint32_t)l2 | ((uint32_t)l3 << 16));
        }
        // ---- copy pre-formatted B planes (PS shorts = 2176 uint4 each) ----
        {
            const uint4* shi = (const uint4*)wf;
            const uint4* slo = (const uint4*)(wf + PS);
            uint4* dhi = (uint4*)Bhi;
            uint4* dlo = (uint4*)Blo;
#pragma unroll
            for (int i = 0; i < 8; i++) {
                dhi[i * 256 + t] = shi[i * 256 + t];
                dlo[i * 256 + t] = slo[i * 256 + t];
            }
            if (t < 128) {
                dhi[2048 + t] = shi[2048 + t];
                dlo[2048 + t] = slo[2048 + t];
            }
        }
        __syncthreads();

        // ---- 3 split terms x 8 k-steps of 16 ----
        for (int p = 0; p < 3; p++) {
            const unsigned short* pA = (p == 2) ? Alo : Ahi;
            const unsigned short* pB = (p == 1) ? Blo : Bhi;
#pragma unroll
            for (int k0 = 0; k0 < 128; k0 += 16) {
                const int ca = k0 + 2 * tq;
                uint32_t b0[4], b1[4];
#pragma unroll
                for (int na = 0; na < 4; na++) {
                    const unsigned short* bp = &pB[(n0 + na * 8 + g) * ROWP + ca];
                    b0[na] = *(const uint32_t*)bp;
                    b1[na] = *(const uint32_t*)(bp + 8);
                }
#pragma unroll
                for (int ma = 0; ma < 2; ma++) {
                    const unsigned short* ap = &pA[(r0 + ma * 16 + g) * ROWP + ca];
                    uint32_t a0 = *(const uint32_t*)ap;
                    uint32_t a1 = *(const uint32_t*)(ap + 8 * ROWP);
                    uint32_t a2 = *(const uint32_t*)(ap + 8);
                    uint32_t a3 = *(const uint32_t*)(ap + 8 * ROWP + 8);
#pragma unroll
                    for (int na = 0; na < 4; na++)
                        mma16816(acc[ma][na], a0, a1, a2, a3, b0[na], b1[na]);
                }
            }
        }
        __syncthreads();
    }

    // ---- epilogue: bias + act, direct float2 stores ----
#pragma unroll
    for (int ma = 0; ma < 2; ma++) {
#pragma unroll
        for (int na = 0; na < 4; na++) {
            int row = m0 + r0 + ma * 16 + g;
            int col = n0 + na * 8 + 2 * tq;
            float bx = __ldg(&bias[col]);
            float by = __ldg(&bias[col + 1]);
            if (row < M) {
                float x = acc[ma][na][0] + bx;
                float y = acc[ma][na][1] + by;
                if (RELU) { x = fmaxf(x, 0.f); y = fmaxf(y, 0.f); }
                *(float2*)&C[(long)row * 128 + col] = make_float2(x, y);
            }
            if (row + 8 < M) {
                float x = acc[ma][na][2] + bx;
                float y = acc[ma][na][3] + by;
                if (RELU) { x = fmaxf(x, 0.f); y = fmaxf(y, 0.f); }
                *(float2*)&C[(long)(row + 8) * 128 + col] = make_float2(x, y);
            }
        }
    }
}

// -------------------- max-pool over S neighbors (warp per node) --------------
__global__ void maxpool_kernel(const float* __restrict__ H,
                               const int* __restrict__ idx,
                               float* __restrict__ out)
{
    int w = (blockIdx.x * blockDim.x + threadIdx.x) >> 5;
    if (w >= NNODES) return;
    int lane = threadIdx.x & 31;
    const int* ip = idx + (long)w * S;
    float4 m = make_float4(-FLT_MAX, -FLT_MAX, -FLT_MAX, -FLT_MAX);
#pragma unroll 5
    for (int s = 0; s < S; s++) {
        int r = __ldg(&ip[s]);
        float4 v = *(const float4*)&H[(long)r * D + lane * 4];
        m.x = fmaxf(m.x, v.x); m.y = fmaxf(m.y, v.y);
        m.z = fmaxf(m.z, v.z); m.w = fmaxf(m.w, v.w);
    }
    *(float4*)&out[(long)w * D + lane * 4] = m;
}

// -------------------- BN stats (deterministic two-stage) ---------------------
__global__ void stats_partial_kernel()
{
    int c = threadIdx.x;
    float s = 0.f, s2 = 0.f;
    for (int r = blockIdx.x; r < NNODES; r += NPART) {
        float v = g_x[(long)r * D + c];
        s += v;
        s2 += v * v;
    }
    g_part[blockIdx.x * (2 * D) + c] = s;
    g_part[blockIdx.x * (2 * D) + D + c] = s2;
}

__global__ void stats_final_kernel(const float* __restrict__ gamma,
                                   const float* __restrict__ beta)
{
    int c = threadIdx.x;
    float s = 0.f, s2 = 0.f;
    for (int b = 0; b < NPART; b++) {
        s += g_part[b * (2 * D) + c];
        s2 += g_part[b * (2 * D) + D + c];
    }
    float invn = 1.f / (float)NNODES;
    float mean = s * invn;
    float var = s2 * invn - mean * mean;
    float sc = gamma[c] * rsqrtf(var + 1e-5f);
    g_scale[c] = sc;
    g_shift[c] = fmaf(-mean, sc, beta[c]);
}

// -------------------- BN apply + L2 row-normalize ----------------------------
__global__ void bn_norm_kernel(const float* __restrict__ X,
                               float* __restrict__ out)
{
    int w = (blockIdx.x * blockDim.x + threadIdx.x) >> 5;
    if (w >= NNODES) return;
    int lane = threadIdx.x & 31;
    int c = lane * 4;
    float4 v = *(const float4*)&X[(long)w * D + c];
    float4 sc = *(const float4*)&g_scale[c];
    float4 sh = *(const float4*)&g_shift[c];
    v.x = fmaf(v.x, sc.x, sh.x);
    v.y = fmaf(v.y, sc.y, sh.y);
    v.z = fmaf(v.z, sc.z, sh.z);
    v.w = fmaf(v.w, sc.w, sh.w);
    float ss = v.x * v.x + v.y * v.y + v.z * v.z + v.w * v.w;
#pragma unroll
    for (int o = 16; o > 0; o >>= 1) ss += __shfl_xor_sync(0xffffffffu, ss, o);
    float inv = 1.f / (sqrtf(ss) + 1e-6f);
    v.x *= inv; v.y *= inv; v.z *= inv; v.w *= inv;
    *(float4*)&out[(long)w * D + c] = v;
}

// -------------------- launch -------------------------------------------------
extern "C" void kernel_launch(void* const* d_in, const int* in_sizes, int n_in,
                              void* d_out, int out_size)
{
    const float* features = (const float*)d_in[0];
    const int*   idx1     = (const int*)d_in[1];
    const int*   idx2     = (const int*)d_in[2];
    const float* agg1_W   = (const float*)d_in[3];
    const float* agg1_b   = (const float*)d_in[4];
    const float* fc1_W    = (const float*)d_in[5];
    const float* fc1_b    = (const float*)d_in[6];
    const float* agg2_W   = (const float*)d_in[7];
    const float* agg2_b   = (const float*)d_in[8];
    const float* fc2_W    = (const float*)d_in[9];
    const float* fc2_b    = (const float*)d_in[10];
    const float* gamma    = (const float*)d_in[11];
    const float* beta     = (const float*)d_in[12];
    float* out = (float*)d_out;

    float *ph, *pagg, *px, *pxn;
    unsigned short* pwf;
    cudaGetSymbolAddress((void**)&ph, g_h);
    cudaGetSymbolAddress((void**)&pagg, g_agg);
    cudaGetSymbolAddress((void**)&px, g_x);
    cudaGetSymbolAddress((void**)&pxn, g_xn);
    cudaGetSymbolAddress((void**)&pwf, g_wfmt);

    cudaFuncSetAttribute(hmma_gemm<128, true>,  cudaFuncAttributeMaxDynamicSharedMemorySize, SMEM_TOTAL);
    cudaFuncSetAttribute(hmma_gemm<256, true>,  cudaFuncAttributeMaxDynamicSharedMemorySize, SMEM_TOTAL);
    cudaFuncSetAttribute(hmma_gemm<256, false>, cudaFuncAttributeMaxDynamicSharedMemorySize, SMEM_TOTAL);

    const unsigned short* wf_agg1 = pwf + 0 * (2 * PS);
    const unsigned short* wf_fc1a = pwf + 1 * (2 * PS);
    const unsigned short* wf_fc1b = pwf + 2 * (2 * PS);
    const unsigned short* wf_agg2 = pwf + 3 * (2 * PS);
    const unsigned short* wf_fc2a = pwf + 4 * (2 * PS);
    const unsigned short* wf_fc2b = pwf + 5 * (2 * PS);

    const int gemm_grid = (NNODES + BLKM - 1) / BLKM;    // 782
    const int warp_grid = (NNODES * 32 + 255) / 256;     // 6250

    prep_weights<<<6, 256>>>(agg1_W, fc1_W, agg2_W, fc2_W);

    // ---- layer 1 ----
    hmma_gemm<128, true><<<gemm_grid, 256, SMEM_TOTAL>>>(features, nullptr, wf_agg1, nullptr, agg1_b, ph, NNODES);
    maxpool_kernel<<<warp_grid, 256>>>(ph, idx1, pagg);
    hmma_gemm<256, true><<<gemm_grid, 256, SMEM_TOTAL>>>(features, pagg, wf_fc1a, wf_fc1b, fc1_b, px, NNODES);
    stats_partial_kernel<<<NPART, D>>>();
    stats_final_kernel<<<1, D>>>(gamma, beta);
    bn_norm_kernel<<<warp_grid, 256>>>(px, pxn);
    // ---- layer 2 ----
    hmma_gemm<128, true><<<gemm_grid, 256, SMEM_TOTAL>>>(pxn, nullptr, wf_agg2, nullptr, agg2_b, ph, NNODES);
    maxpool_kernel<<<warp_grid, 256>>>(ph, idx2, pagg);
    hmma_gemm<256, false><<<gemm_grid, 256, SMEM_TOTAL>>>(pxn, pagg, wf_fc2a, wf_fc2b, fc2_b, out, NNODES);
}

// round 16
// speedup vs baseline: 1.6155x; 1.1374x over previous
#include <cuda_runtime.h>
#include <cuda_bf16.h>
#include <stdint.h>
#include <math.h>
#include <float.h>

#define NNODES 50000
#define NPAD   50048                // padded to multiple of 64 rows
#define D 128
#define S 25
#define NPART 512

#define ROWP 136                    // padded row length in bf16 elems (128 + 8)
#define PS   (128 * ROWP)           // B plane size in shorts = 17408
#define BLKM 64
#define APS  (BLKM * ROWP)          // A tile plane size in shorts = 8704

// -------------------- scratch (device globals; no allocation) ----------------
__device__ float g_h[NNODES * D];           // relu(linear) table for maxpool
__device__ float g_x[NNODES * D];           // fc1 output (pre-BN), for stats
__device__ float g_part[NPART * 2 * D];
__device__ float g_scale[D];
__device__ float g_shift[D];
// bf16 hi/lo activation planes, ROWP-padded rows (GEMM A operands)
__device__ __align__(16) unsigned short g_feat_hi[NPAD * ROWP];
__device__ __align__(16) unsigned short g_feat_lo[NPAD * ROWP];
__device__ __align__(16) unsigned short g_agg_hi[NPAD * ROWP];
__device__ __align__(16) unsigned short g_agg_lo[NPAD * ROWP];
__device__ __align__(16) unsigned short g_xn_hi[NPAD * ROWP];
__device__ __align__(16) unsigned short g_xn_lo[NPAD * ROWP];
// 6 weight K-chunks (agg1, fc1a, fc1b, agg2, fc2a, fc2b) x {hi,lo} planes
__device__ __align__(16) unsigned short g_wfmt[6 * 2 * PS];

__device__ __forceinline__ unsigned short bf16_hi(float x) {
    return __bfloat16_as_ushort(__float2bfloat16(x));
}
__device__ __forceinline__ float bf16_val(unsigned short u) {
    return __bfloat162float(__ushort_as_bfloat16(u));
}
__device__ __forceinline__ uint32_t smem_u32(const void* p) {
    uint32_t a;
    asm("{ .reg .u64 t; cvta.to.shared.u64 t, %1; cvt.u32.u64 %0, t; }" : "=r"(a) : "l"(p));
    return a;
}
#define CP_ASYNC16(dst_u32, src_ptr) \
    asm volatile("cp.async.cg.shared.global [%0], [%1], 16;" :: "r"(dst_u32), "l"(src_ptr))
#define CP_COMMIT() asm volatile("cp.async.commit_group;" ::: "memory")
#define CP_WAIT0()  asm volatile("cp.async.wait_group 0;" ::: "memory")

// split one float4 into packed hi/lo bf16x2 pairs
__device__ __forceinline__ void split4(float4 v, uint2& hi, uint2& lo) {
    unsigned short h0 = bf16_hi(v.x), h1 = bf16_hi(v.y), h2 = bf16_hi(v.z), h3 = bf16_hi(v.w);
    unsigned short l0 = bf16_hi(v.x - bf16_val(h0));
    unsigned short l1 = bf16_hi(v.y - bf16_val(h1));
    unsigned short l2 = bf16_hi(v.z - bf16_val(h2));
    unsigned short l3 = bf16_hi(v.w - bf16_val(h3));
    hi = make_uint2((uint32_t)h0 | ((uint32_t)h1 << 16), (uint32_t)h2 | ((uint32_t)h3 << 16));
    lo = make_uint2((uint32_t)l0 | ((uint32_t)l1 << 16), (uint32_t)l2 | ((uint32_t)l3 << 16));
}

// -------------------- weight pre-format (once per launch) --------------------
// Plane layout: Bs[n][k] = W[kc+k][n], rows padded to ROWP shorts.
__global__ void prep_weights(const float* __restrict__ agg1W, const float* __restrict__ fc1W,
                             const float* __restrict__ agg2W, const float* __restrict__ fc2W)
{
    int b = blockIdx.x;
    const float* W; int kc;
    switch (b) {
        case 0: W = agg1W; kc = 0;   break;
        case 1: W = fc1W;  kc = 0;   break;
        case 2: W = fc1W;  kc = 128; break;
        case 3: W = agg2W; kc = 0;   break;
        case 4: W = fc2W;  kc = 0;   break;
        default: W = fc2W; kc = 128; break;
    }
    unsigned short* hi = g_wfmt + (b * 2 + 0) * PS;
    unsigned short* lo = g_wfmt + (b * 2 + 1) * PS;
    int t = threadIdx.x;
    int n  = t & 127;
    int k0 = (t >> 7) * 64;
    for (int k = 0; k < 64; k++) {
        float x = W[(long)(kc + k0 + k) * 128 + n];
        unsigned short h = bf16_hi(x);
        unsigned short l = bf16_hi(x - bf16_val(h));
        hi[n * ROWP + k0 + k] = h;
        lo[n * ROWP + k0 + k] = l;
    }
}

// -------------------- feature convert (once per launch) ----------------------
__global__ void prep_feat(const float* __restrict__ F)
{
    int idx = blockIdx.x * blockDim.x + threadIdx.x;    // one float4 each
    if (idx >= NNODES * 32) return;
    int row = idx >> 5;
    int c4  = (idx & 31) << 2;
    float4 v = *(const float4*)&F[(long)row * 128 + c4];
    uint2 hi, lo;
    split4(v, hi, lo);
    int o = row * ROWP + c4;
    *(uint2*)&g_feat_hi[o] = hi;
    *(uint2*)&g_feat_lo[o] = lo;
}

// -------------------- HMMA (mma.sync) helpers --------------------------------
__device__ __forceinline__ void mma16816(float* c,
                                         uint32_t a0, uint32_t a1, uint32_t a2, uint32_t a3,
                                         uint32_t b0, uint32_t b1)
{
    asm volatile(
        "mma.sync.aligned.m16n8k16.row.col.f32.bf16.bf16.f32 "
        "{%0,%1,%2,%3}, {%4,%5,%6,%7}, {%8,%9}, {%0,%1,%2,%3};"
        : "+f"(c[0]), "+f"(c[1]), "+f"(c[2]), "+f"(c[3])
        : "r"(a0), "r"(a1), "r"(a2), "r"(a3), "r"(b0), "r"(b1));
}

// -------------------- HMMA GEMM ----------------------------------------------
// C[M,128] = act( [A0|A1][M,KTOT] @ W[KTOT,128] + b ), KTOT in {128,256}
// A operands are pre-split bf16 hi/lo planes (ROWP-padded); pure cp.async fills.
// 3-term split fused per k-step: AhiBhi + AhiBlo + AloBhi (fp32 accum).
#define SMEM_TOTAL ((2 * APS + 2 * PS) * 2)   // 104448 B -> 2 CTAs/SM

template <int KTOT, bool RELU>
__global__ __launch_bounds__(256) void hmma_gemm(
    const unsigned short* __restrict__ a0hi, const unsigned short* __restrict__ a0lo,
    const unsigned short* __restrict__ a1hi, const unsigned short* __restrict__ a1lo,
    const unsigned short* __restrict__ wf0,   // [hi PS][lo PS] chunk0
    const unsigned short* __restrict__ wf1,   // chunk1 (or null)
    const float* __restrict__ bias, float* __restrict__ C, int M)
{
    extern __shared__ __align__(16) unsigned short sm[];
    unsigned short* Ahi = sm;
    unsigned short* Alo = sm + APS;
    unsigned short* Bhi = sm + 2 * APS;
    unsigned short* Blo = sm + 2 * APS + PS;

    const int t    = threadIdx.x;
    const int w    = t >> 5;
    const int lane = t & 31;
    const int g    = lane >> 2;        // group id (0..7)
    const int tq   = lane & 3;         // thread-in-group
    const int r0   = (w & 1) * 32;     // warp M offset within tile
    const int n0   = (w >> 1) * 32;    // warp N offset
    const int m0   = blockIdx.x * BLKM;

    const uint32_t sAhi = smem_u32(Ahi), sAlo = smem_u32(Alo);
    const uint32_t sBhi = smem_u32(Bhi), sBlo = smem_u32(Blo);

    float acc[2][4][4];
#pragma unroll
    for (int ma = 0; ma < 2; ma++)
#pragma unroll
        for (int na = 0; na < 4; na++)
#pragma unroll
            for (int q = 0; q < 4; q++) acc[ma][na][q] = 0.f;

    const int NCHUNK = KTOT / 128;
    for (int ch = 0; ch < NCHUNK; ch++) {
        const unsigned short* ahi = (ch == 0) ? a0hi : a1hi;
        const unsigned short* alo = (ch == 0) ? a0lo : a1lo;
        const unsigned short* wf  = (ch == 0) ? wf0 : wf1;

        // ---- async fills: A planes (1088 uint4 each), B planes (2176 each) ----
        {
            const uint4* gah = (const uint4*)(ahi + (long)m0 * ROWP);
            const uint4* gal = (const uint4*)(alo + (long)m0 * ROWP);
#pragma unroll
            for (int i = 0; i < 4; i++) {
                int j = i * 256 + t;
                CP_ASYNC16(sAhi + j * 16, gah + j);
                CP_ASYNC16(sAlo + j * 16, gal + j);
            }
            if (t < 64) {
                int j = 1024 + t;
                CP_ASYNC16(sAhi + j * 16, gah + j);
                CP_ASYNC16(sAlo + j * 16, gal + j);
            }
            const uint4* gbh = (const uint4*)wf;
            const uint4* gbl = (const uint4*)(wf + PS);
#pragma unroll
            for (int i = 0; i < 8; i++) {
                int j = i * 256 + t;
                CP_ASYNC16(sBhi + j * 16, gbh + j);
                CP_ASYNC16(sBlo + j * 16, gbl + j);
            }
            if (t < 128) {
                int j = 2048 + t;
                CP_ASYNC16(sBhi + j * 16, gbh + j);
                CP_ASYNC16(sBlo + j * 16, gbl + j);
            }
            CP_COMMIT();
            CP_WAIT0();
        }
        __syncthreads();

        // ---- fused 3-term mainloop: 8 k-steps of 16 ----
#pragma unroll
        for (int k0 = 0; k0 < 128; k0 += 16) {
            const int ca = k0 + 2 * tq;
            uint32_t bh0[4], bh1[4], bl0[4], bl1[4];
#pragma unroll
            for (int na = 0; na < 4; na++) {
                const int bo = (n0 + na * 8 + g) * ROWP + ca;
                bh0[na] = *(const uint32_t*)&Bhi[bo];
                bh1[na] = *(const uint32_t*)&Bhi[bo + 8];
                bl0[na] = *(const uint32_t*)&Blo[bo];
                bl1[na] = *(const uint32_t*)&Blo[bo + 8];
            }
#pragma unroll
            for (int ma = 0; ma < 2; ma++) {
                const int ao = (r0 + ma * 16 + g) * ROWP + ca;
                uint32_t h0 = *(const uint32_t*)&Ahi[ao];
                uint32_t h1 = *(const uint32_t*)&Ahi[ao + 8 * ROWP];
                uint32_t h2 = *(const uint32_t*)&Ahi[ao + 8];
                uint32_t h3 = *(const uint32_t*)&Ahi[ao + 8 * ROWP + 8];
                uint32_t l0 = *(const uint32_t*)&Alo[ao];
                uint32_t l1 = *(const uint32_t*)&Alo[ao + 8 * ROWP];
                uint32_t l2 = *(const uint32_t*)&Alo[ao + 8];
                uint32_t l3 = *(const uint32_t*)&Alo[ao + 8 * ROWP + 8];
#pragma unroll
                for (int na = 0; na < 4; na++) {
                    mma16816(acc[ma][na], h0, h1, h2, h3, bh0[na], bh1[na]);
                    mma16816(acc[ma][na], h0, h1, h2, h3, bl0[na], bl1[na]);
                    mma16816(acc[ma][na], l0, l1, l2, l3, bh0[na], bh1[na]);
                }
            }
        }
        if (ch + 1 < NCHUNK) __syncthreads();
    }

    // ---- epilogue: bias + act, direct float2 stores ----
#pragma unroll
    for (int ma = 0; ma < 2; ma++) {
#pragma unroll
        for (int na = 0; na < 4; na++) {
            int row = m0 + r0 + ma * 16 + g;
            int col = n0 + na * 8 + 2 * tq;
            float bx = __ldg(&bias[col]);
            float by = __ldg(&bias[col + 1]);
            if (row < M) {
                float x = acc[ma][na][0] + bx;
                float y = acc[ma][na][1] + by;
                if (RELU) { x = fmaxf(x, 0.f); y = fmaxf(y, 0.f); }
                *(float2*)&C[(long)row * 128 + col] = make_float2(x, y);
            }
            if (row + 8 < M) {
                float x = acc[ma][na][2] + bx;
                float y = acc[ma][na][3] + by;
                if (RELU) { x = fmaxf(x, 0.f); y = fmaxf(y, 0.f); }
                *(float2*)&C[(long)(row + 8) * 128 + col] = make_float2(x, y);
            }
        }
    }
}

// -------------------- max-pool: warp per node, emits hi/lo planes ------------
__global__ void maxpool_kernel(const float* __restrict__ H,
                               const int* __restrict__ idx,
                               unsigned short* __restrict__ ohi,
                               unsigned short* __restrict__ olo)
{
    int w = (blockIdx.x * blockDim.x + threadIdx.x) >> 5;
    if (w >= NNODES) return;
    int lane = threadIdx.x & 31;
    const int* ip = idx + (long)w * S;
    float4 m = make_float4(-FLT_MAX, -FLT_MAX, -FLT_MAX, -FLT_MAX);
#pragma unroll 5
    for (int s = 0; s < S; s++) {
        int r = __ldg(&ip[s]);
        float4 v = *(const float4*)&H[(long)r * D + lane * 4];
        m.x = fmaxf(m.x, v.x); m.y = fmaxf(m.y, v.y);
        m.z = fmaxf(m.z, v.z); m.w = fmaxf(m.w, v.w);
    }
    uint2 hi, lo;
    split4(m, hi, lo);
    int o = w * ROWP + lane * 4;
    *(uint2*)&ohi[o] = hi;
    *(uint2*)&olo[o] = lo;
}

// -------------------- BN stats (deterministic two-stage) ---------------------
__global__ void stats_partial_kernel()
{
    int c = threadIdx.x;
    float s = 0.f, s2 = 0.f;
    for (int r = blockIdx.x; r < NNODES; r += NPART) {
        float v = g_x[(long)r * D + c];
        s += v;
        s2 += v * v;
    }
    g_part[blockIdx.x * (2 * D) + c] = s;
    g_part[blockIdx.x * (2 * D) + D + c] = s2;
}

__global__ void stats_final_kernel(const float* __restrict__ gamma,
                                   const float* __restrict__ beta)
{
    int c = threadIdx.x;
    float s = 0.f, s2 = 0.f;
    for (int b = 0; b < NPART; b++) {
        s += g_part[b * (2 * D) + c];
        s2 += g_part[b * (2 * D) + D + c];
    }
    float invn = 1.f / (float)NNODES;
    float mean = s * invn;
    float var = s2 * invn - mean * mean;
    float sc = gamma[c] * rsqrtf(var + 1e-5f);
    g_scale[c] = sc;
    g_shift[c] = fmaf(-mean, sc, beta[c]);
}

// -------------------- BN apply + L2 row-normalize -> hi/lo planes ------------
__global__ void bn_norm_kernel(const float* __restrict__ X)
{
    int w = (blockIdx.x * blockDim.x + threadIdx.x) >> 5;
    if (w >= NNODES) return;
    int lane = threadIdx.x & 31;
    int c = lane * 4;
    float4 v = *(const float4*)&X[(long)w * D + c];
    float4 sc = *(const float4*)&g_scale[c];
    float4 sh = *(const float4*)&g_shift[c];
    v.x = fmaf(v.x, sc.x, sh.x);
    v.y = fmaf(v.y, sc.y, sh.y);
    v.z = fmaf(v.z, sc.z, sh.z);
    v.w = fmaf(v.w, sc.w, sh.w);
    float ss = v.x * v.x + v.y * v.y + v.z * v.z + v.w * v.w;
#pragma unroll
    for (int o = 16; o > 0; o >>= 1) ss += __shfl_xor_sync(0xffffffffu, ss, o);
    float inv = 1.f / (sqrtf(ss) + 1e-6f);
    v.x *= inv; v.y *= inv; v.z *= inv; v.w *= inv;
    uint2 hi, lo;
    split4(v, hi, lo);
    int o = w * ROWP + c;
    *(uint2*)&g_xn_hi[o] = hi;
    *(uint2*)&g_xn_lo[o] = lo;
}

// -------------------- launch -------------------------------------------------
extern "C" void kernel_launch(void* const* d_in, const int* in_sizes, int n_in,
                              void* d_out, int out_size)
{
    const float* features = (const float*)d_in[0];
    const int*   idx1     = (const int*)d_in[1];
    const int*   idx2     = (const int*)d_in[2];
    const float* agg1_W   = (const float*)d_in[3];
    const float* agg1_b   = (const float*)d_in[4];
    const float* fc1_W    = (const float*)d_in[5];
    const float* fc1_b    = (const float*)d_in[6];
    const float* agg2_W   = (const float*)d_in[7];
    const float* agg2_b   = (const float*)d_in[8];
    const float* fc2_W    = (const float*)d_in[9];
    const float* fc2_b    = (const float*)d_in[10];
    const float* gamma    = (const float*)d_in[11];
    const float* beta     = (const float*)d_in[12];
    float* out = (float*)d_out;

    float *ph, *px;
    unsigned short *pwf, *pfh, *pfl, *pah, *pal, *pxh, *pxl;
    cudaGetSymbolAddress((void**)&ph, g_h);
    cudaGetSymbolAddress((void**)&px, g_x);
    cudaGetSymbolAddress((void**)&pwf, g_wfmt);
    cudaGetSymbolAddress((void**)&pfh, g_feat_hi);
    cudaGetSymbolAddress((void**)&pfl, g_feat_lo);
    cudaGetSymbolAddress((void**)&pah, g_agg_hi);
    cudaGetSymbolAddress((void**)&pal, g_agg_lo);
    cudaGetSymbolAddress((void**)&pxh, g_xn_hi);
    cudaGetSymbolAddress((void**)&pxl, g_xn_lo);

    cudaFuncSetAttribute(hmma_gemm<128, true>,  cudaFuncAttributeMaxDynamicSharedMemorySize, SMEM_TOTAL);
    cudaFuncSetAttribute(hmma_gemm<256, true>,  cudaFuncAttributeMaxDynamicSharedMemorySize, SMEM_TOTAL);
    cudaFuncSetAttribute(hmma_gemm<256, false>, cudaFuncAttributeMaxDynamicSharedMemorySize, SMEM_TOTAL);

    const unsigned short* wf_agg1 = pwf + 0 * (2 * PS);
    const unsigned short* wf_fc1a = pwf + 1 * (2 * PS);
    const unsigned short* wf_fc1b = pwf + 2 * (2 * PS);
    const unsigned short* wf_agg2 = pwf + 3 * (2 * PS);
    const unsigned short* wf_fc2a = pwf + 4 * (2 * PS);
    const unsigned short* wf_fc2b = pwf + 5 * (2 * PS);

    const int gemm_grid = (NNODES + BLKM - 1) / BLKM;    // 782
    const int warp_grid = (NNODES * 32 + 255) / 256;     // 6250

    prep_weights<<<6, 256>>>(agg1_W, fc1_W, agg2_W, fc2_W);
    prep_feat<<<(NNODES * 32 + 255) / 256, 256>>>(features);

    // ---- layer 1 ----
    hmma_gemm<128, true><<<gemm_grid, 256, SMEM_TOTAL>>>(
        pfh, pfl, nullptr, nullptr, wf_agg1, nullptr, agg1_b, ph, NNODES);
    maxpool_kernel<<<warp_grid, 256>>>(ph, idx1, pah, pal);
    hmma_gemm<256, true><<<gemm_grid, 256, SMEM_TOTAL>>>(
        pfh, pfl, pah, pal, wf_fc1a, wf_fc1b, fc1_b, px, NNODES);
    stats_partial_kernel<<<NPART, D>>>();
    stats_final_kernel<<<1, D>>>(gamma, beta);
    bn_norm_kernel<<<warp_grid, 256>>>(px);
    // ---- layer 2 ----
    hmma_gemm<128, true><<<gemm_grid, 256, SMEM_TOTAL>>>(
        pxh, pxl, nullptr, nullptr, wf_agg2, nullptr, agg2_b, ph, NNODES);
    maxpool_kernel<<<warp_grid, 256>>>(ph, idx2, pah, pal);
    hmma_gemm<256, false><<<gemm_grid, 256, SMEM_TOTAL>>>(
        pxh, pxl, pah, pal, wf_fc2a, wf_fc2b, fc2_b, out, NNODES);
}

// round 17
// speedup vs baseline: 1.6368x; 1.0132x over previous
#include <cuda_runtime.h>
#include <cuda_bf16.h>
#include <stdint.h>
#include <math.h>
#include <float.h>

#define NNODES 50000
#define NPAD   50048                // padded to multiple of 64 rows
#define D 128
#define S 25

#define ROWP 136                    // padded row length in bf16 elems (128 + 8)
#define PS   (128 * ROWP)           // B plane size in shorts = 17408
#define BLKM 64
#define APS  (BLKM * ROWP)          // A tile plane size in shorts = 8704
#define GRIDM (NPAD / BLKM)         // 782 GEMM blocks

// -------------------- scratch (device globals; no allocation) ----------------
__device__ float g_h[NNODES * D];           // relu(linear) table for maxpool
__device__ float g_x[NNODES * D];           // fc1 output (pre-BN)
__device__ float g_part[GRIDM * 256];       // per-CTA BN partials [block][sum 128 | sumsq 128]
__device__ float g_scale[D];
__device__ float g_shift[D];
// bf16 hi/lo activation planes, ROWP-padded rows (GEMM A operands)
__device__ __align__(16) unsigned short g_feat_hi[NPAD * ROWP];
__device__ __align__(16) unsigned short g_feat_lo[NPAD * ROWP];
__device__ __align__(16) unsigned short g_agg_hi[NPAD * ROWP];
__device__ __align__(16) unsigned short g_agg_lo[NPAD * ROWP];
__device__ __align__(16) unsigned short g_xn_hi[NPAD * ROWP];
__device__ __align__(16) unsigned short g_xn_lo[NPAD * ROWP];
// 6 weight K-chunks (agg1, fc1a, fc1b, agg2, fc2a, fc2b) x {hi,lo} planes
__device__ __align__(16) unsigned short g_wfmt[6 * 2 * PS];

__device__ __forceinline__ unsigned short bf16_hi(float x) {
    return __bfloat16_as_ushort(__float2bfloat16(x));
}
__device__ __forceinline__ float bf16_val(unsigned short u) {
    return __bfloat162float(__ushort_as_bfloat16(u));
}
__device__ __forceinline__ uint32_t smem_u32(const void* p) {
    uint32_t a;
    asm("{ .reg .u64 t; cvta.to.shared.u64 t, %1; cvt.u32.u64 %0, t; }" : "=r"(a) : "l"(p));
    return a;
}
#define CP_ASYNC16(dst_u32, src_ptr) \
    asm volatile("cp.async.cg.shared.global [%0], [%1], 16;" :: "r"(dst_u32), "l"(src_ptr))
#define CP_COMMIT() asm volatile("cp.async.commit_group;" ::: "memory")
#define CP_WAIT0()  asm volatile("cp.async.wait_group 0;" ::: "memory")

// split one float4 into packed hi/lo bf16x2 pairs
__device__ __forceinline__ void split4(float4 v, uint2& hi, uint2& lo) {
    unsigned short h0 = bf16_hi(v.x), h1 = bf16_hi(v.y), h2 = bf16_hi(v.z), h3 = bf16_hi(v.w);
    unsigned short l0 = bf16_hi(v.x - bf16_val(h0));
    unsigned short l1 = bf16_hi(v.y - bf16_val(h1));
    unsigned short l2 = bf16_hi(v.z - bf16_val(h2));
    unsigned short l3 = bf16_hi(v.w - bf16_val(h3));
    hi = make_uint2((uint32_t)h0 | ((uint32_t)h1 << 16), (uint32_t)h2 | ((uint32_t)h3 << 16));
    lo = make_uint2((uint32_t)l0 | ((uint32_t)l1 << 16), (uint32_t)l2 | ((uint32_t)l3 << 16));
}

// -------------------- weight pre-format (once per launch) --------------------
__global__ void prep_weights(const float* __restrict__ agg1W, const float* __restrict__ fc1W,
                             const float* __restrict__ agg2W, const float* __restrict__ fc2W)
{
    int b = blockIdx.x;
    const float* W; int kc;
    switch (b) {
        case 0: W = agg1W; kc = 0;   break;
        case 1: W = fc1W;  kc = 0;   break;
        case 2: W = fc1W;  kc = 128; break;
        case 3: W = agg2W; kc = 0;   break;
        case 4: W = fc2W;  kc = 0;   break;
        default: W = fc2W; kc = 128; break;
    }
    unsigned short* hi = g_wfmt + (b * 2 + 0) * PS;
    unsigned short* lo = g_wfmt + (b * 2 + 1) * PS;
    int t = threadIdx.x;
    int n  = t & 127;
    int k0 = (t >> 7) * 64;
    for (int k = 0; k < 64; k++) {
        float x = W[(long)(kc + k0 + k) * 128 + n];
        unsigned short h = bf16_hi(x);
        unsigned short l = bf16_hi(x - bf16_val(h));
        hi[n * ROWP + k0 + k] = h;
        lo[n * ROWP + k0 + k] = l;
    }
}

// -------------------- feature convert (once per launch) ----------------------
__global__ void prep_feat(const float* __restrict__ F)
{
    int idx = blockIdx.x * blockDim.x + threadIdx.x;    // one float4 each
    if (idx >= NNODES * 32) return;
    int row = idx >> 5;
    int c4  = (idx & 31) << 2;
    float4 v = *(const float4*)&F[(long)row * 128 + c4];
    uint2 hi, lo;
    split4(v, hi, lo);
    int o = row * ROWP + c4;
    *(uint2*)&g_feat_hi[o] = hi;
    *(uint2*)&g_feat_lo[o] = lo;
}

// -------------------- HMMA (mma.sync) helpers --------------------------------
__device__ __forceinline__ void mma16816(float* c,
                                         uint32_t a0, uint32_t a1, uint32_t a2, uint32_t a3,
                                         uint32_t b0, uint32_t b1)
{
    asm volatile(
        "mma.sync.aligned.m16n8k16.row.col.f32.bf16.bf16.f32 "
        "{%0,%1,%2,%3}, {%4,%5,%6,%7}, {%8,%9}, {%0,%1,%2,%3};"
        : "+f"(c[0]), "+f"(c[1]), "+f"(c[2]), "+f"(c[3])
        : "r"(a0), "r"(a1), "r"(a2), "r"(a3), "r"(b0), "r"(b1));
}

// -------------------- HMMA GEMM ----------------------------------------------
// C[M,128] = act( [A0|A1][M,KTOT] @ W[KTOT,128] + b ), KTOT in {128,256}
// A operands are pre-split bf16 hi/lo planes (ROWP-padded); pure cp.async fills.
// 3-term split fused per k-step: AhiBhi + AhiBlo + AloBhi (fp32 accum).
// STATS: deterministic per-CTA BN column partials written to g_part[blockIdx].
#define SMEM_TOTAL ((2 * APS + 2 * PS) * 2)   // 104448 B -> 2 CTAs/SM

template <int KTOT, bool RELU, bool STATS>
__global__ __launch_bounds__(256) void hmma_gemm(
    const unsigned short* __restrict__ a0hi, const unsigned short* __restrict__ a0lo,
    const unsigned short* __restrict__ a1hi, const unsigned short* __restrict__ a1lo,
    const unsigned short* __restrict__ wf0,   // [hi PS][lo PS] chunk0
    const unsigned short* __restrict__ wf1,   // chunk1 (or null)
    const float* __restrict__ bias, float* __restrict__ C, int M)
{
    extern __shared__ __align__(16) unsigned short sm[];
    unsigned short* Ahi = sm;
    unsigned short* Alo = sm + APS;
    unsigned short* Bhi = sm + 2 * APS;
    unsigned short* Blo = sm + 2 * APS + PS;

    const int t    = threadIdx.x;
    const int w    = t >> 5;
    const int lane = t & 31;
    const int g    = lane >> 2;        // group id (0..7)
    const int tq   = lane & 3;         // thread-in-group
    const int r0   = (w & 1) * 32;     // warp M offset within tile
    const int n0   = (w >> 1) * 32;    // warp N offset
    const int m0   = blockIdx.x * BLKM;

    const uint32_t sAhi = smem_u32(Ahi), sAlo = smem_u32(Alo);
    const uint32_t sBhi = smem_u32(Bhi), sBlo = smem_u32(Blo);

    float acc[2][4][4];
#pragma unroll
    for (int ma = 0; ma < 2; ma++)
#pragma unroll
        for (int na = 0; na < 4; na++)
#pragma unroll
            for (int q = 0; q < 4; q++) acc[ma][na][q] = 0.f;

    const int NCHUNK = KTOT / 128;
    for (int ch = 0; ch < NCHUNK; ch++) {
        const unsigned short* ahi = (ch == 0) ? a0hi : a1hi;
        const unsigned short* alo = (ch == 0) ? a0lo : a1lo;
        const unsigned short* wf  = (ch == 0) ? wf0 : wf1;

        // ---- async fills: A planes (1088 uint4 each), B planes (2176 each) ----
        {
            const uint4* gah = (const uint4*)(ahi + (long)m0 * ROWP);
            const uint4* gal = (const uint4*)(alo + (long)m0 * ROWP);
#pragma unroll
            for (int i = 0; i < 4; i++) {
                int j = i * 256 + t;
                CP_ASYNC16(sAhi + j * 16, gah + j);
                CP_ASYNC16(sAlo + j * 16, gal + j);
            }
            if (t < 64) {
                int j = 1024 + t;
                CP_ASYNC16(sAhi + j * 16, gah + j);
                CP_ASYNC16(sAlo + j * 16, gal + j);
            }
            const uint4* gbh = (const uint4*)wf;
            const uint4* gbl = (const uint4*)(wf + PS);
#pragma unroll
            for (int i = 0; i < 8; i++) {
                int j = i * 256 + t;
                CP_ASYNC16(sBhi + j * 16, gbh + j);
                CP_ASYNC16(sBlo + j * 16, gbl + j);
            }
            if (t < 128) {
                int j = 2048 + t;
                CP_ASYNC16(sBhi + j * 16, gbh + j);
                CP_ASYNC16(sBlo + j * 16, gbl + j);
            }
            CP_COMMIT();
            CP_WAIT0();
        }
        __syncthreads();

        // ---- fused 3-term mainloop: 8 k-steps of 16 ----
#pragma unroll
        for (int k0 = 0; k0 < 128; k0 += 16) {
            const int ca = k0 + 2 * tq;
            uint32_t bh0[4], bh1[4], bl0[4], bl1[4];
#pragma unroll
            for (int na = 0; na < 4; na++) {
                const int bo = (n0 + na * 8 + g) * ROWP + ca;
                bh0[na] = *(const uint32_t*)&Bhi[bo];
                bh1[na] = *(const uint32_t*)&Bhi[bo + 8];
                bl0[na] = *(const uint32_t*)&Blo[bo];
                bl1[na] = *(const uint32_t*)&Blo[bo + 8];
            }
#pragma unroll
            for (int ma = 0; ma < 2; ma++) {
                const int ao = (r0 + ma * 16 + g) * ROWP + ca;
                uint32_t h0 = *(const uint32_t*)&Ahi[ao];
                uint32_t h1 = *(const uint32_t*)&Ahi[ao + 8 * ROWP];
                uint32_t h2 = *(const uint32_t*)&Ahi[ao + 8];
                uint32_t h3 = *(const uint32_t*)&Ahi[ao + 8 * ROWP + 8];
                uint32_t l0 = *(const uint32_t*)&Alo[ao];
                uint32_t l1 = *(const uint32_t*)&Alo[ao + 8 * ROWP];
                uint32_t l2 = *(const uint32_t*)&Alo[ao + 8];
                uint32_t l3 = *(const uint32_t*)&Alo[ao + 8 * ROWP + 8];
#pragma unroll
                for (int na = 0; na < 4; na++) {
                    mma16816(acc[ma][na], h0, h1, h2, h3, bh0[na], bh1[na]);
                    mma16816(acc[ma][na], h0, h1, h2, h3, bl0[na], bl1[na]);
                    mma16816(acc[ma][na], l0, l1, l2, l3, bh0[na], bh1[na]);
                }
            }
        }
        if (ch + 1 < NCHUNK) __syncthreads();
    }

    // ---- epilogue: bias + act, direct float2 stores (+ optional BN partials) --
    float sc[8], sq[8];
    if (STATS) {
#pragma unroll
        for (int j = 0; j < 8; j++) { sc[j] = 0.f; sq[j] = 0.f; }
    }
#pragma unroll
    for (int ma = 0; ma < 2; ma++) {
#pragma unroll
        for (int na = 0; na < 4; na++) {
            int row = m0 + r0 + ma * 16 + g;
            int col = n0 + na * 8 + 2 * tq;
            float bx = __ldg(&bias[col]);
            float by = __ldg(&bias[col + 1]);
            if (row < M) {
                float x = acc[ma][na][0] + bx;
                float y = acc[ma][na][1] + by;
                if (RELU) { x = fmaxf(x, 0.f); y = fmaxf(y, 0.f); }
                *(float2*)&C[(long)row * 128 + col] = make_float2(x, y);
                if (STATS) {
                    sc[na * 2 + 0] += x; sq[na * 2 + 0] += x * x;
                    sc[na * 2 + 1] += y; sq[na * 2 + 1] += y * y;
                }
            }
            if (row + 8 < M) {
                float x = acc[ma][na][2] + bx;
                float y = acc[ma][na][3] + by;
                if (RELU) { x = fmaxf(x, 0.f); y = fmaxf(y, 0.f); }
                *(float2*)&C[(long)(row + 8) * 128 + col] = make_float2(x, y);
                if (STATS) {
                    sc[na * 2 + 0] += x; sq[na * 2 + 0] += x * x;
                    sc[na * 2 + 1] += y; sq[na * 2 + 1] += y * y;
                }
            }
        }
    }

    if (STATS) {
        // reduce over g-lanes (rows) -> warp col sums for 32 rows
#pragma unroll
        for (int o = 4; o <= 16; o <<= 1) {
#pragma unroll
            for (int j = 0; j < 8; j++) {
                sc[j] += __shfl_xor_sync(0xffffffffu, sc[j], o);
                sq[j] += __shfl_xor_sync(0xffffffffu, sq[j], o);
            }
        }
        __syncthreads();                       // all warps done with smem planes
        float* spS = (float*)sm;               // [8 warps][32 cols]
        float* spQ = (float*)sm + 256;
        if (g == 0) {
#pragma unroll
            for (int j = 0; j < 8; j++) {
                int cl = (j >> 1) * 8 + 2 * tq + (j & 1);
                spS[w * 32 + cl] = sc[j];
                spQ[w * 32 + cl] = sq[j];
            }
        }
        __syncthreads();
        if (t < 128) {
            int half = t >> 5;                 // which 32-col group
            int cl = t & 31;
            float s = spS[(2 * half) * 32 + cl] + spS[(2 * half + 1) * 32 + cl];
            float q = spQ[(2 * half) * 32 + cl] + spQ[(2 * half + 1) * 32 + cl];
            g_part[blockIdx.x * 256 + t] = s;
            g_part[blockIdx.x * 256 + 128 + t] = q;
        }
    }
}

// -------------------- max-pool: warp per node, emits hi/lo planes ------------
__global__ void maxpool_kernel(const float* __restrict__ H,
                               const int* __restrict__ idx,
                               unsigned short* __restrict__ ohi,
                               unsigned short* __restrict__ olo)
{
    int w = (blockIdx.x * blockDim.x + threadIdx.x) >> 5;
    if (w >= NNODES) return;
    int lane = threadIdx.x & 31;
    const int* ip = idx + (long)w * S;
    float4 m = make_float4(-FLT_MAX, -FLT_MAX, -FLT_MAX, -FLT_MAX);
#pragma unroll
    for (int s = 0; s < S; s++) {
        int r = __ldg(&ip[s]);
        float4 v = *(const float4*)&H[(long)r * D + lane * 4];
        m.x = fmaxf(m.x, v.x); m.y = fmaxf(m.y, v.y);
        m.z = fmaxf(m.z, v.z); m.w = fmaxf(m.w, v.w);
    }
    uint2 hi, lo;
    split4(m, hi, lo);
    int o = w * ROWP + lane * 4;
    *(uint2*)&ohi[o] = hi;
    *(uint2*)&olo[o] = lo;
}

// -------------------- BN stats final (deterministic fixed-order sum) ---------
__global__ void stats_final_kernel(const float* __restrict__ gamma,
                                   const float* __restrict__ beta)
{
    __shared__ float red[256];
    int t = threadIdx.x;          // 256 threads: t<128 sums, t>=128 sumsqs
    int c = t & 127;
    int off = (t >> 7) * 128;
    float s = 0.f;
    for (int b = 0; b < GRIDM; b++)
        s += g_part[b * 256 + off + c];
    red[t] = s;
    __syncthreads();
    if (t < 128) {
        float sum = red[t], sum2 = red[128 + t];
        float invn = 1.f / (float)NNODES;
        float mean = sum * invn;
        float var = sum2 * invn - mean * mean;
        float scl = gamma[t] * rsqrtf(var + 1e-5f);
        g_scale[t] = scl;
        g_shift[t] = fmaf(-mean, scl, beta[t]);
    }
}

// -------------------- BN apply + L2 row-normalize -> hi/lo planes ------------
__global__ void bn_norm_kernel(const float* __restrict__ X)
{
    int w = (blockIdx.x * blockDim.x + threadIdx.x) >> 5;
    if (w >= NNODES) return;
    int lane = threadIdx.x & 31;
    int c = lane * 4;
    float4 v = *(const float4*)&X[(long)w * D + c];
    float4 sc = *(const float4*)&g_scale[c];
    float4 sh = *(const float4*)&g_shift[c];
    v.x = fmaf(v.x, sc.x, sh.x);
    v.y = fmaf(v.y, sc.y, sh.y);
    v.z = fmaf(v.z, sc.z, sh.z);
    v.w = fmaf(v.w, sc.w, sh.w);
    float ss = v.x * v.x + v.y * v.y + v.z * v.z + v.w * v.w;
#pragma unroll
    for (int o = 16; o > 0; o >>= 1) ss += __shfl_xor_sync(0xffffffffu, ss, o);
    float inv = 1.f / (sqrtf(ss) + 1e-6f);
    v.x *= inv; v.y *= inv; v.z *= inv; v.w *= inv;
    uint2 hi, lo;
    split4(v, hi, lo);
    int o = w * ROWP + c;
    *(uint2*)&g_xn_hi[o] = hi;
    *(uint2*)&g_xn_lo[o] = lo;
}

// -------------------- launch -------------------------------------------------
extern "C" void kernel_launch(void* const* d_in, const int* in_sizes, int n_in,
                              void* d_out, int out_size)
{
    const float* features = (const float*)d_in[0];
    const int*   idx1     = (const int*)d_in[1];
    const int*   idx2     = (const int*)d_in[2];
    const float* agg1_W   = (const float*)d_in[3];
    const float* agg1_b   = (const float*)d_in[4];
    const float* fc1_W    = (const float*)d_in[5];
    const float* fc1_b    = (const float*)d_in[6];
    const float* agg2_W   = (const float*)d_in[7];
    const float* agg2_b   = (const float*)d_in[8];
    const float* fc2_W    = (const float*)d_in[9];
    const float* fc2_b    = (const float*)d_in[10];
    const float* gamma    = (const float*)d_in[11];
    const float* beta     = (const float*)d_in[12];
    float* out = (float*)d_out;

    float *ph, *px;
    unsigned short *pwf, *pfh, *pfl, *pah, *pal, *pxh, *pxl;
    cudaGetSymbolAddress((void**)&ph, g_h);
    cudaGetSymbolAddress((void**)&px, g_x);
    cudaGetSymbolAddress((void**)&pwf, g_wfmt);
    cudaGetSymbolAddress((void**)&pfh, g_feat_hi);
    cudaGetSymbolAddress((void**)&pfl, g_feat_lo);
    cudaGetSymbolAddress((void**)&pah, g_agg_hi);
    cudaGetSymbolAddress((void**)&pal, g_agg_lo);
    cudaGetSymbolAddress((void**)&pxh, g_xn_hi);
    cudaGetSymbolAddress((void**)&pxl, g_xn_lo);

    cudaFuncSetAttribute(hmma_gemm<128, true,  false>, cudaFuncAttributeMaxDynamicSharedMemorySize, SMEM_TOTAL);
    cudaFuncSetAttribute(hmma_gemm<256, true,  true>,  cudaFuncAttributeMaxDynamicSharedMemorySize, SMEM_TOTAL);
    cudaFuncSetAttribute(hmma_gemm<256, false, false>, cudaFuncAttributeMaxDynamicSharedMemorySize, SMEM_TOTAL);

    const unsigned short* wf_agg1 = pwf + 0 * (2 * PS);
    const unsigned short* wf_fc1a = pwf + 1 * (2 * PS);
    const unsigned short* wf_fc1b = pwf + 2 * (2 * PS);
    const unsigned short* wf_agg2 = pwf + 3 * (2 * PS);
    const unsigned short* wf_fc2a = pwf + 4 * (2 * PS);
    const unsigned short* wf_fc2b = pwf + 5 * (2 * PS);

    const int warp_grid = (NNODES * 32 + 255) / 256;     // 6250

    prep_weights<<<6, 256>>>(agg1_W, fc1_W, agg2_W, fc2_W);
    prep_feat<<<(NNODES * 32 + 255) / 256, 256>>>(features);

    // ---- layer 1 ----
    hmma_gemm<128, true, false><<<GRIDM, 256, SMEM_TOTAL>>>(
        pfh, pfl, nullptr, nullptr, wf_agg1, nullptr, agg1_b, ph, NNODES);
    maxpool_kernel<<<warp_grid, 256>>>(ph, idx1, pah, pal);
    hmma_gemm<256, true, true><<<GRIDM, 256, SMEM_TOTAL>>>(
        pfh, pfl, pah, pal, wf_fc1a, wf_fc1b, fc1_b, px, NNODES);
    stats_final_kernel<<<1, 256>>>(gamma, beta);
    bn_norm_kernel<<<warp_grid, 256>>>(px);
    // ---- layer 2 ----
    hmma_gemm<128, true, false><<<GRIDM, 256, SMEM_TOTAL>>>(
        pxh, pxl, nullptr, nullptr, wf_agg2, nullptr, agg2_b, ph, NNODES);
    maxpool_kernel<<<warp_grid, 256>>>(ph, idx2, pah, pal);
    hmma_gemm<256, false, false><<<GRIDM, 256, SMEM_TOTAL>>>(
        pxh, pxl, pah, pal, wf_fc2a, wf_fc2b, fc2_b, out, NNODES);
}